// round 12
// baseline (speedup 1.0000x reference)
#include <cuda_runtime.h>
#include <cuda_fp16.h>
#include <cstdint>

#define THREADS 512
#define ROWSPB  128

// ---- smem byte offsets (from 128-aligned base) ----
#define OFF_AHI  0              // 128x256 fp16 packed blocks: 65536
#define OFF_WB   65536          // 4 buffers x 8192
#define OFF_W1S  98304          // 8192
#define OFF_B1S  106496
#define OFF_B2S  107520
#define OFF_B3S  108544
#define OFF_W4S  109056
#define OFF_B4S  110592
#define OFF_PART 110608         // 128*12 floats = 6144
#define OFF_MB   116752         // full[4] cons[4] = 64
#define SMEM_BYTES (116816 + 256)

// weight image (fp16): W2 = 16 k16-chunks x 8192; W3 at 131072 = 16 x 4096
#define IMG3 131072
__device__ __align__(16) unsigned char g_wimg[131072 + 65536];

// ---------------- helpers ----------------
__device__ __forceinline__ uint32_t smem_u32(const void* p) {
    uint32_t a;
    asm("{ .reg .u64 t; cvta.to.shared.u64 t, %1; cvt.u32.u64 %0, t; }" : "=r"(a) : "l"(p));
    return a;
}

#define MBARRIER_INIT(addr, cnt) \
    asm volatile("mbarrier.init.shared.b64 [%0], %1;" :: "r"((uint32_t)(addr)), "r"((uint32_t)(cnt)) : "memory")
#define MBARRIER_ARRIVE(addr) \
    asm volatile("mbarrier.arrive.shared.b64 _, [%0];" :: "r"((uint32_t)(addr)) : "memory")
#define MBARRIER_EXPECT_TX(addr, bytes) \
    asm volatile("mbarrier.arrive.expect_tx.shared.b64 _, [%0], %1;" :: "r"((uint32_t)(addr)), "r"((uint32_t)(bytes)) : "memory")
#define MBARRIER_WAIT_PARITY(addr, parity) do {                                   \
    uint32_t _mb = (uint32_t)(addr); uint32_t _p = (uint32_t)(parity);            \
    asm volatile(                                                                 \
        "{\n\t.reg .pred P;\n\t"                                                  \
        "WL_%=:\n\t"                                                              \
        "mbarrier.try_wait.parity.acquire.cta.shared::cta.b64 P, [%0], %1, 0x989680;\n\t" \
        "@P bra.uni WD_%=;\n\t"                                                   \
        "bra.uni WL_%=;\n\t"                                                      \
        "WD_%=:\n\t}"                                                             \
        :: "r"(_mb), "r"(_p) : "memory");                                         \
} while (0)
#define FENCE_PROXY_ASYNC() asm volatile("fence.proxy.async.shared::cta;" ::: "memory")

__device__ __forceinline__ void bulk_copy(uint32_t smem_dst, const void* gsrc,
                                          uint32_t bytes, uint32_t mbar) {
    uint64_t g = (uint64_t)__cvta_generic_to_global(gsrc);
    asm volatile(
        "cp.async.bulk.shared::cta.global.mbarrier::complete_tx::bytes [%0], [%1], %2, [%3];"
        :: "r"(smem_dst), "l"(g), "r"(bytes), "r"(mbar) : "memory");
}

__device__ __forceinline__ void ldsm4(uint32_t a, uint32_t* r) {
    asm volatile("ldmatrix.sync.aligned.m8n8.x4.shared.b16 {%0,%1,%2,%3}, [%4];"
        : "=r"(r[0]), "=r"(r[1]), "=r"(r[2]), "=r"(r[3]) : "r"(a));
}

__device__ __forceinline__ void mma16816(float* d, const uint32_t* a, uint32_t b0, uint32_t b1) {
    asm("mma.sync.aligned.m16n8k16.row.col.f32.f16.f16.f32 "
        "{%0,%1,%2,%3}, {%4,%5,%6,%7}, {%8,%9}, {%0,%1,%2,%3};"
        : "+f"(d[0]), "+f"(d[1]), "+f"(d[2]), "+f"(d[3])
        : "r"(a[0]), "r"(a[1]), "r"(a[2]), "r"(a[3]), "r"(b0), "r"(b1));
}

__device__ __forceinline__ float silu_f(float x) {
    return __fdividef(x, 1.0f + __expf(-x));
}

// packed-block byte offset for A: (m,k) in 128x256, blocks 16x16 = 4 contiguous 8x8 tiles
__device__ __forceinline__ uint32_t a_off(int m, int k) {
    return (uint32_t)((m >> 4) * 8192 + (k >> 4) * 512 +
           (((m & 8) >> 3) + ((k & 8) >> 3) * 2) * 128 + (m & 7) * 16 + (k & 7) * 2);
}

// ---------------- prologue: convert + pack weights (fp16) ----------------
__global__ void prep_weights(const float* __restrict__ W2, const float* __restrict__ W3) {
    int idx = blockIdx.x * blockDim.x + threadIdx.x;
    if (idx >= 98304) return;
    float w; size_t off;
    if (idx < 65536) {                   // W2[n][k]
        int n = idx >> 8, k = idx & 255;
        w = W2[idx];
        int u = ((n & 8) >> 3) * 2 + ((k & 8) >> 3);
        off = (size_t)(k >> 4) * 8192 + (size_t)(n >> 4) * 512 + u * 128 + (n & 7) * 16 + (k & 7) * 2;
    } else {                             // W3[n][k], n<128
        int i = idx - 65536;
        int n = i >> 8, k = i & 255;
        w = W3[i];
        int u = ((n & 8) >> 3) * 2 + ((k & 8) >> 3);
        off = IMG3 + (size_t)(k >> 4) * 4096 + (size_t)(n >> 4) * 512 + u * 128 + (n & 7) * 16 + (k & 7) * 2;
    }
    *(__half*)(g_wimg + off) = __float2half_rn(w);
}

// ---------------- main kernel ----------------
extern "C" __global__ void __launch_bounds__(THREADS, 1)
mdp_mma_kernel(const float* __restrict__ log_p,
               const float* __restrict__ log_y,
               const float* __restrict__ log_xb,
               const float* __restrict__ log_q,
               const float* __restrict__ W1, const float* __restrict__ b1,
               const float* __restrict__ b2, const float* __restrict__ b3,
               const float* __restrict__ W4, const float* __restrict__ b4,
               const float* __restrict__ log_beta,
               const float* __restrict__ log_delta,
               float* __restrict__ out)
{
    extern __shared__ unsigned char dynsm[];
    const uint32_t raw = smem_u32(dynsm);
    const uint32_t abase = (raw + 127u) & ~127u;
    unsigned char* sm = dynsm + (abase - raw);

    float* W1s = (float*)(sm + OFF_W1S);
    float* b1s = (float*)(sm + OFF_B1S);
    float* b2s = (float*)(sm + OFF_B2S);
    float* b3s = (float*)(sm + OFF_B3S);
    float* W4s = (float*)(sm + OFF_W4S);
    float* b4s = (float*)(sm + OFF_B4S);
    float* part = (float*)(sm + OFF_PART);

    const uint32_t uAH = abase + OFF_AHI;
    const uint32_t uWB = abase + OFF_WB;
    const uint32_t mbF = abase + OFF_MB;        // full[i] at +8*i
    const uint32_t mbC = abase + OFF_MB + 32;   // cons[i] at +8*i

    const int tid  = threadIdx.x;
    const int wid  = tid >> 5;
    const int lane = tid & 31;
    const int row0 = blockIdx.x * ROWSPB;

    const float delta = 1.0f / (1.0f + __expf(-log_delta[0]));
    float beta = __expf(log_beta[0]);
    beta = fminf(fmaxf(beta, 0.5f), 20.0f);

    // init barriers + kick off first 4 chunk loads
    if (tid == 0) {
        #pragma unroll
        for (int i = 0; i < 4; i++) {
            MBARRIER_INIT(mbF + 8 * i, 1);
            MBARRIER_INIT(mbC + 8 * i, 16);
        }
        FENCE_PROXY_ASYNC();
        #pragma unroll
        for (int i = 0; i < 4; i++) {
            MBARRIER_EXPECT_TX(mbF + 8 * i, 8192);
            bulk_copy(uWB + i * 8192, g_wimg + (size_t)i * 8192, 8192, mbF + 8 * i);
        }
    }

    // stage small params
    for (int i = tid; i < 2048; i += THREADS) {
        const int k = i >> 3, c = i & 7;
        W1s[i] = (c < 7) ? W1[k * 7 + c] : 0.0f;
    }
    if (tid < 256) { b1s[tid] = b1[tid]; b2s[tid] = b2[tid]; }
    if (tid < 128) b3s[tid] = b3[tid];
    if (tid < 384) W4s[tid] = W4[tid];
    if (tid < 3)   b4s[tid] = b4[tid];
    __syncthreads();

    // ---- layer 1 (fp32 exact) -> packed A fp16 ----
    {
        const int m  = tid & 127;
        const int k0 = (tid >> 7) * 64;
        const int r  = row0 + m;
        float x0 = log_p[r * 3 + 0], x1 = log_p[r * 3 + 1], x2 = log_p[r * 3 + 2];
        float x3 = log_y[r];
        float x4 = delta * log_xb[r * 3 + 0] + (1.0f - delta) * log_q[r * 3 + 0];
        float x5 = delta * log_xb[r * 3 + 1] + (1.0f - delta) * log_q[r * 3 + 1];
        float x6 = delta * log_xb[r * 3 + 2] + (1.0f - delta) * log_q[r * 3 + 2];
        #pragma unroll 8
        for (int j = 0; j < 64; j += 2) {
            const int k = k0 + j;
            const float4 w0 = *(const float4*)&W1s[k * 8];
            const float4 w1 = *(const float4*)&W1s[k * 8 + 4];
            const float4 u0 = *(const float4*)&W1s[(k + 1) * 8];
            const float4 u1 = *(const float4*)&W1s[(k + 1) * 8 + 4];
            const float2 bb = *(const float2*)&b1s[k];
            float v0 = bb.x, v1 = bb.y;
            v0 = fmaf(x0, w0.x, v0); v1 = fmaf(x0, u0.x, v1);
            v0 = fmaf(x1, w0.y, v0); v1 = fmaf(x1, u0.y, v1);
            v0 = fmaf(x2, w0.z, v0); v1 = fmaf(x2, u0.z, v1);
            v0 = fmaf(x3, w0.w, v0); v1 = fmaf(x3, u0.w, v1);
            v0 = fmaf(x4, w1.x, v0); v1 = fmaf(x4, u1.x, v1);
            v0 = fmaf(x5, w1.y, v0); v1 = fmaf(x5, u1.y, v1);
            v0 = fmaf(x6, w1.z, v0); v1 = fmaf(x6, u1.z, v1);
            v0 = silu_f(v0); v1 = silu_f(v1);
            __half2 h = __floats2half2_rn(v0, v1);
            *(uint32_t*)(sm + OFF_AHI + a_off(m, k)) = *reinterpret_cast<uint32_t*>(&h);
        }
    }
    __syncthreads();

    // warp tiling: 4m x 4n
    const int mw = wid & 3;
    const int nw = wid >> 2;
    const int mrow = mw * 32;
    const uint32_t aB0 = uAH + (uint32_t)(mw * 2) * 8192 + (uint32_t)lane * 16;
    const uint32_t aB1 = aB0 + 8192;

    // ================= layer 2: C[128,256], warp tile 32x64 =================
    float acc[64];
    #pragma unroll
    for (int i = 0; i < 64; i++) acc[i] = 0.0f;

    for (int ci = 0; ci < 16; ci++) {
        const int buf = ci & 3;
        const int par = (ci >> 2) & 1;

        // A fragments don't depend on streamed buffer: load before the wait
        const uint32_t koff = (uint32_t)ci * 512;
        uint32_t ah0[4], ah1[4];
        ldsm4(aB0 + koff, ah0);
        ldsm4(aB1 + koff, ah1);

        MBARRIER_WAIT_PARITY(mbF + 8 * buf, par);

        const uint32_t bBase = uWB + (uint32_t)buf * 8192 + (uint32_t)(nw * 4) * 512 + (uint32_t)lane * 16;
        uint32_t bh[16];
        #pragma unroll
        for (int g = 0; g < 4; g++) ldsm4(bBase + g * 512, bh + 4 * g);

        #pragma unroll
        for (int g = 0; g < 4; g++) {
            mma16816(&acc[g * 16 + 0],  ah0, bh[4 * g + 0], bh[4 * g + 1]);
            mma16816(&acc[g * 16 + 4],  ah0, bh[4 * g + 2], bh[4 * g + 3]);
            mma16816(&acc[g * 16 + 8],  ah1, bh[4 * g + 0], bh[4 * g + 1]);
            mma16816(&acc[g * 16 + 12], ah1, bh[4 * g + 2], bh[4 * g + 3]);
        }

        if (lane == 0) MBARRIER_ARRIVE(mbC + 8 * buf);
        if (tid == 0 && ci + 4 < 32) {
            MBARRIER_WAIT_PARITY(mbC + 8 * buf, par);
            const int nx = ci + 4;
            const uint32_t sz = (nx < 16) ? 8192u : 4096u;
            const unsigned char* src = (nx < 16) ? (g_wimg + (size_t)nx * 8192)
                                                 : (g_wimg + IMG3 + (size_t)(nx - 16) * 4096);
            MBARRIER_EXPECT_TX(mbF + 8 * buf, sz);
            bulk_copy(uWB + (uint32_t)buf * 8192, src, sz, mbF + 8 * buf);
        }
    }
    __syncthreads();   // everyone done reading A before overwrite

    // epilogue: silu(acc + b2) -> packed A fp16
    {
        const int rbase = mrow + (lane >> 2);
        const int cbase = 2 * (lane & 3);
        #pragma unroll
        for (int g = 0; g < 4; g++) {
            #pragma unroll
            for (int m2 = 0; m2 < 2; m2++) {
                #pragma unroll
                for (int h = 0; h < 2; h++) {
                    const int idx = g * 16 + m2 * 8 + h * 4;
                    const int col = nw * 64 + g * 16 + h * 8 + cbase;
                    const float2 bb2 = *(const float2*)&b2s[col];
                    float v0 = silu_f(acc[idx + 0] + bb2.x);
                    float v1 = silu_f(acc[idx + 1] + bb2.y);
                    __half2 hh = __floats2half2_rn(v0, v1);
                    *(uint32_t*)(sm + OFF_AHI + a_off(rbase + m2 * 16, col)) =
                        *reinterpret_cast<uint32_t*>(&hh);
                    float v2 = silu_f(acc[idx + 2] + bb2.x);
                    float v3 = silu_f(acc[idx + 3] + bb2.y);
                    hh = __floats2half2_rn(v2, v3);
                    *(uint32_t*)(sm + OFF_AHI + a_off(rbase + m2 * 16 + 8, col)) =
                        *reinterpret_cast<uint32_t*>(&hh);
                }
            }
        }
    }
    __syncthreads();

    // ================= layer 3: C[128,128], warp tile 32x32 =================
    float acc3[32];
    #pragma unroll
    for (int i = 0; i < 32; i++) acc3[i] = 0.0f;

    for (int ci = 16; ci < 32; ci++) {
        const int buf = ci & 3;
        const int par = (ci >> 2) & 1;

        const uint32_t koff = (uint32_t)(ci - 16) * 512;
        uint32_t ah0[4], ah1[4];
        ldsm4(aB0 + koff, ah0);
        ldsm4(aB1 + koff, ah1);

        MBARRIER_WAIT_PARITY(mbF + 8 * buf, par);

        const uint32_t bBase = uWB + (uint32_t)buf * 8192 + (uint32_t)(nw * 2) * 512 + (uint32_t)lane * 16;
        uint32_t bh[8];
        #pragma unroll
        for (int g = 0; g < 2; g++) ldsm4(bBase + g * 512, bh + 4 * g);
        #pragma unroll
        for (int g = 0; g < 2; g++) {
            mma16816(&acc3[g * 16 + 0],  ah0, bh[4 * g + 0], bh[4 * g + 1]);
            mma16816(&acc3[g * 16 + 4],  ah0, bh[4 * g + 2], bh[4 * g + 3]);
            mma16816(&acc3[g * 16 + 8],  ah1, bh[4 * g + 0], bh[4 * g + 1]);
            mma16816(&acc3[g * 16 + 12], ah1, bh[4 * g + 2], bh[4 * g + 3]);
        }

        if (lane == 0) MBARRIER_ARRIVE(mbC + 8 * buf);
        if (tid == 0 && ci + 4 < 32) {
            MBARRIER_WAIT_PARITY(mbC + 8 * buf, par);
            const int nx = ci + 4;
            MBARRIER_EXPECT_TX(mbF + 8 * buf, 4096);
            bulk_copy(uWB + (uint32_t)buf * 8192,
                      g_wimg + IMG3 + (size_t)(nx - 16) * 4096, 4096, mbF + 8 * buf);
        }
    }

    // ---- layer 4 partials from registers: silu(acc3+b3) . W4 ----
    {
        float p[4][3];
        #pragma unroll
        for (int s = 0; s < 4; s++) { p[s][0] = 0.f; p[s][1] = 0.f; p[s][2] = 0.f; }
        const int cb = 2 * (lane & 3);
        #pragma unroll
        for (int g = 0; g < 2; g++) {
            #pragma unroll
            for (int m2 = 0; m2 < 2; m2++) {
                #pragma unroll
                for (int h = 0; h < 2; h++) {
                    const int idx = g * 16 + m2 * 8 + h * 4;
                    const int col = nw * 32 + g * 16 + h * 8 + cb;
                    const float2 bb3 = *(const float2*)&b3s[col];
                    #pragma unroll
                    for (int j = 0; j < 4; j++) {
                        const int c = col + (j & 1);
                        const float v = silu_f(acc3[idx + j] + ((j & 1) ? bb3.y : bb3.x));
                        const int slot = m2 * 2 + (j >> 1);
                        p[slot][0] = fmaf(v, W4s[c],       p[slot][0]);
                        p[slot][1] = fmaf(v, W4s[128 + c], p[slot][1]);
                        p[slot][2] = fmaf(v, W4s[256 + c], p[slot][2]);
                    }
                }
            }
        }
        #pragma unroll
        for (int s = 0; s < 4; s++)
            #pragma unroll
            for (int g = 0; g < 3; g++) {
                p[s][g] += __shfl_xor_sync(0xffffffffu, p[s][g], 1);
                p[s][g] += __shfl_xor_sync(0xffffffffu, p[s][g], 2);
            }
        if ((lane & 3) == 0) {
            const int r = lane >> 2;
            #pragma unroll
            for (int s = 0; s < 4; s++) {
                const int row = mrow + (s >> 1) * 16 + (s & 1) * 8 + r;
                part[row * 12 + nw * 3 + 0] = p[s][0];
                part[row * 12 + nw * 3 + 1] = p[s][1];
                part[row * 12 + nw * 3 + 2] = p[s][2];
            }
        }
    }
    __syncthreads();

    // ---- softmax + store ----
    if (tid < ROWSPB) {
        const int m = tid;
        float l0 = b4s[0], l1 = b4s[1], l2 = b4s[2];
        #pragma unroll
        for (int c = 0; c < 4; c++) {
            l0 += part[m * 12 + c * 3 + 0];
            l1 += part[m * 12 + c * 3 + 1];
            l2 += part[m * 12 + c * 3 + 2];
        }
        l0 *= beta; l1 *= beta; l2 *= beta;
        const float mx = fmaxf(l0, fmaxf(l1, l2));
        const float e0 = __expf(l0 - mx);
        const float e1 = __expf(l1 - mx);
        const float e2 = __expf(l2 - mx);
        const float inv = __frcp_rn(e0 + e1 + e2);
        const int r = row0 + m;
        out[r * 3 + 0] = e0 * inv;
        out[r * 3 + 1] = e1 * inv;
        out[r * 3 + 2] = e2 * inv;
    }
}

extern "C" void kernel_launch(void* const* d_in, const int* in_sizes, int n_in,
                              void* d_out, int out_size)
{
    const float* log_p     = (const float*)d_in[0];
    const float* log_y     = (const float*)d_in[1];
    const float* log_xb    = (const float*)d_in[2];
    const float* log_q     = (const float*)d_in[3];
    const float* W1        = (const float*)d_in[4];
    const float* b1        = (const float*)d_in[5];
    const float* W2        = (const float*)d_in[6];
    const float* b2        = (const float*)d_in[7];
    const float* W3        = (const float*)d_in[8];
    const float* b3        = (const float*)d_in[9];
    const float* W4        = (const float*)d_in[10];
    const float* b4        = (const float*)d_in[11];
    const float* log_beta  = (const float*)d_in[12];
    const float* log_delta = (const float*)d_in[13];
    float* out = (float*)d_out;

    const int B = in_sizes[1];
    const int grid = B / ROWSPB;

    prep_weights<<<96, 1024>>>(W2, W3);

    cudaFuncSetAttribute(mdp_mma_kernel,
                         cudaFuncAttributeMaxDynamicSharedMemorySize, SMEM_BYTES);

    mdp_mma_kernel<<<grid, THREADS, SMEM_BYTES>>>(
        log_p, log_y, log_xb, log_q,
        W1, b1, b2, b3, W4, b4,
        log_beta, log_delta, out);
}

// round 13
// speedup vs baseline: 1.0004x; 1.0004x over previous
#include <cuda_runtime.h>
#include <cuda_fp16.h>
#include <cstdint>

#define THREADS 512
#define ROWSPB  128

// ---- smem byte offsets (from 128-aligned base) ----
#define OFF_AHI  0              // 128x256 fp16 packed blocks: 65536
#define OFF_WB   65536          // 4 buffers x 8192
#define OFF_W1S  98304          // 8192
#define OFF_B1S  106496
#define OFF_B2S  107520
#define OFF_B3S  108544
#define OFF_W4S  109056
#define OFF_B4S  110592
#define OFF_PART 110608         // 128*12 floats = 6144
#define OFF_MB   116752         // full[4] cons[4] = 64
#define SMEM_BYTES (116816 + 256)

// weight image (fp16): W2 = 16 k16-chunks x 8192; W3 at 131072 = 16 x 4096
#define IMG3 131072
__device__ __align__(16) unsigned char g_wimg[131072 + 65536];

// ---------------- helpers ----------------
__device__ __forceinline__ uint32_t smem_u32(const void* p) {
    uint32_t a;
    asm("{ .reg .u64 t; cvta.to.shared.u64 t, %1; cvt.u32.u64 %0, t; }" : "=r"(a) : "l"(p));
    return a;
}

#define MBARRIER_INIT(addr, cnt) \
    asm volatile("mbarrier.init.shared.b64 [%0], %1;" :: "r"((uint32_t)(addr)), "r"((uint32_t)(cnt)) : "memory")
#define MBARRIER_ARRIVE(addr) \
    asm volatile("mbarrier.arrive.shared.b64 _, [%0];" :: "r"((uint32_t)(addr)) : "memory")
#define MBARRIER_EXPECT_TX(addr, bytes) \
    asm volatile("mbarrier.arrive.expect_tx.shared.b64 _, [%0], %1;" :: "r"((uint32_t)(addr)), "r"((uint32_t)(bytes)) : "memory")
#define MBARRIER_WAIT_PARITY(addr, parity) do {                                   \
    uint32_t _mb = (uint32_t)(addr); uint32_t _p = (uint32_t)(parity);            \
    asm volatile(                                                                 \
        "{\n\t.reg .pred P;\n\t"                                                  \
        "WL_%=:\n\t"                                                              \
        "mbarrier.try_wait.parity.acquire.cta.shared::cta.b64 P, [%0], %1, 0x989680;\n\t" \
        "@P bra.uni WD_%=;\n\t"                                                   \
        "bra.uni WL_%=;\n\t"                                                      \
        "WD_%=:\n\t}"                                                             \
        :: "r"(_mb), "r"(_p) : "memory");                                         \
} while (0)
#define FENCE_PROXY_ASYNC() asm volatile("fence.proxy.async.shared::cta;" ::: "memory")

__device__ __forceinline__ void bulk_copy(uint32_t smem_dst, const void* gsrc,
                                          uint32_t bytes, uint32_t mbar) {
    uint64_t g = (uint64_t)__cvta_generic_to_global(gsrc);
    asm volatile(
        "cp.async.bulk.shared::cta.global.mbarrier::complete_tx::bytes [%0], [%1], %2, [%3];"
        :: "r"(smem_dst), "l"(g), "r"(bytes), "r"(mbar) : "memory");
}

__device__ __forceinline__ void ldsm4(uint32_t a, uint32_t* r) {
    asm volatile("ldmatrix.sync.aligned.m8n8.x4.shared.b16 {%0,%1,%2,%3}, [%4];"
        : "=r"(r[0]), "=r"(r[1]), "=r"(r[2]), "=r"(r[3]) : "r"(a));
}

__device__ __forceinline__ void mma16816(float* d, const uint32_t* a, uint32_t b0, uint32_t b1) {
    asm("mma.sync.aligned.m16n8k16.row.col.f32.f16.f16.f32 "
        "{%0,%1,%2,%3}, {%4,%5,%6,%7}, {%8,%9}, {%0,%1,%2,%3};"
        : "+f"(d[0]), "+f"(d[1]), "+f"(d[2]), "+f"(d[3])
        : "r"(a[0]), "r"(a[1]), "r"(a[2]), "r"(a[3]), "r"(b0), "r"(b1));
}

__device__ __forceinline__ float silu_f(float x) {
    return __fdividef(x, 1.0f + __expf(-x));
}

// packed-block byte offset for A: (m,k) in 128x256, blocks 16x16 = 4 contiguous 8x8 tiles
__device__ __forceinline__ uint32_t a_off(int m, int k) {
    return (uint32_t)((m >> 4) * 8192 + (k >> 4) * 512 +
           (((m & 8) >> 3) + ((k & 8) >> 3) * 2) * 128 + (m & 7) * 16 + (k & 7) * 2);
}

// ---------------- prologue: convert + pack weights (fp16) ----------------
__global__ void prep_weights(const float* __restrict__ W2, const float* __restrict__ W3) {
    int idx = blockIdx.x * blockDim.x + threadIdx.x;
    if (idx >= 98304) return;
    float w; size_t off;
    if (idx < 65536) {                   // W2[n][k]
        int n = idx >> 8, k = idx & 255;
        w = W2[idx];
        int u = ((n & 8) >> 3) * 2 + ((k & 8) >> 3);
        off = (size_t)(k >> 4) * 8192 + (size_t)(n >> 4) * 512 + u * 128 + (n & 7) * 16 + (k & 7) * 2;
    } else {                             // W3[n][k], n<128
        int i = idx - 65536;
        int n = i >> 8, k = i & 255;
        w = W3[i];
        int u = ((n & 8) >> 3) * 2 + ((k & 8) >> 3);
        off = IMG3 + (size_t)(k >> 4) * 4096 + (size_t)(n >> 4) * 512 + u * 128 + (n & 7) * 16 + (k & 7) * 2;
    }
    *(__half*)(g_wimg + off) = __float2half_rn(w);
}

// ---------------- main kernel ----------------
extern "C" __global__ void __launch_bounds__(THREADS, 1)
mdp_mma_kernel(const float* __restrict__ log_p,
               const float* __restrict__ log_y,
               const float* __restrict__ log_xb,
               const float* __restrict__ log_q,
               const float* __restrict__ W1, const float* __restrict__ b1,
               const float* __restrict__ b2, const float* __restrict__ b3,
               const float* __restrict__ W4, const float* __restrict__ b4,
               const float* __restrict__ log_beta,
               const float* __restrict__ log_delta,
               float* __restrict__ out)
{
    extern __shared__ unsigned char dynsm[];
    const uint32_t raw = smem_u32(dynsm);
    const uint32_t abase = (raw + 127u) & ~127u;
    unsigned char* sm = dynsm + (abase - raw);

    float* W1s = (float*)(sm + OFF_W1S);
    float* b1s = (float*)(sm + OFF_B1S);
    float* b2s = (float*)(sm + OFF_B2S);
    float* b3s = (float*)(sm + OFF_B3S);
    float* W4s = (float*)(sm + OFF_W4S);
    float* b4s = (float*)(sm + OFF_B4S);
    float* part = (float*)(sm + OFF_PART);

    const uint32_t uAH = abase + OFF_AHI;
    const uint32_t uWB = abase + OFF_WB;
    const uint32_t mbF = abase + OFF_MB;        // full[i] at +8*i
    const uint32_t mbC = abase + OFF_MB + 32;   // cons[i] at +8*i

    const int tid  = threadIdx.x;
    const int wid  = tid >> 5;
    const int lane = tid & 31;
    const int row0 = blockIdx.x * ROWSPB;

    const float delta = 1.0f / (1.0f + __expf(-log_delta[0]));
    float beta = __expf(log_beta[0]);
    beta = fminf(fmaxf(beta, 0.5f), 20.0f);

    // init barriers + kick off first 4 chunk loads
    if (tid == 0) {
        #pragma unroll
        for (int i = 0; i < 4; i++) {
            MBARRIER_INIT(mbF + 8 * i, 1);
            MBARRIER_INIT(mbC + 8 * i, 16);
        }
        FENCE_PROXY_ASYNC();
        #pragma unroll
        for (int i = 0; i < 4; i++) {
            MBARRIER_EXPECT_TX(mbF + 8 * i, 8192);
            bulk_copy(uWB + i * 8192, g_wimg + (size_t)i * 8192, 8192, mbF + 8 * i);
        }
    }

    // stage small params
    for (int i = tid; i < 2048; i += THREADS) {
        const int k = i >> 3, c = i & 7;
        W1s[i] = (c < 7) ? W1[k * 7 + c] : 0.0f;
    }
    if (tid < 256) { b1s[tid] = b1[tid]; b2s[tid] = b2[tid]; }
    if (tid < 128) b3s[tid] = b3[tid];
    if (tid < 384) W4s[tid] = W4[tid];
    if (tid < 3)   b4s[tid] = b4[tid];
    __syncthreads();

    // ---- layer 1 (fp32 exact) -> packed A fp16 ----
    {
        const int m  = tid & 127;
        const int k0 = (tid >> 7) * 64;
        const int r  = row0 + m;
        float x0 = log_p[r * 3 + 0], x1 = log_p[r * 3 + 1], x2 = log_p[r * 3 + 2];
        float x3 = log_y[r];
        float x4 = delta * log_xb[r * 3 + 0] + (1.0f - delta) * log_q[r * 3 + 0];
        float x5 = delta * log_xb[r * 3 + 1] + (1.0f - delta) * log_q[r * 3 + 1];
        float x6 = delta * log_xb[r * 3 + 2] + (1.0f - delta) * log_q[r * 3 + 2];
        #pragma unroll 8
        for (int j = 0; j < 64; j += 2) {
            const int k = k0 + j;
            const float4 w0 = *(const float4*)&W1s[k * 8];
            const float4 w1 = *(const float4*)&W1s[k * 8 + 4];
            const float4 u0 = *(const float4*)&W1s[(k + 1) * 8];
            const float4 u1 = *(const float4*)&W1s[(k + 1) * 8 + 4];
            const float2 bb = *(const float2*)&b1s[k];
            float v0 = bb.x, v1 = bb.y;
            v0 = fmaf(x0, w0.x, v0); v1 = fmaf(x0, u0.x, v1);
            v0 = fmaf(x1, w0.y, v0); v1 = fmaf(x1, u0.y, v1);
            v0 = fmaf(x2, w0.z, v0); v1 = fmaf(x2, u0.z, v1);
            v0 = fmaf(x3, w0.w, v0); v1 = fmaf(x3, u0.w, v1);
            v0 = fmaf(x4, w1.x, v0); v1 = fmaf(x4, u1.x, v1);
            v0 = fmaf(x5, w1.y, v0); v1 = fmaf(x5, u1.y, v1);
            v0 = fmaf(x6, w1.z, v0); v1 = fmaf(x6, u1.z, v1);
            v0 = silu_f(v0); v1 = silu_f(v1);
            __half2 h = __floats2half2_rn(v0, v1);
            *(uint32_t*)(sm + OFF_AHI + a_off(m, k)) = *reinterpret_cast<uint32_t*>(&h);
        }
    }
    __syncthreads();

    // warp tiling: 4m x 4n
    const int mw = wid & 3;
    const int nw = wid >> 2;
    const int mrow = mw * 32;
    const uint32_t aB0 = uAH + (uint32_t)(mw * 2) * 8192 + (uint32_t)lane * 16;
    const uint32_t aB1 = aB0 + 8192;

    // ================= layer 2: C[128,256], warp tile 32x64 =================
    float acc[64];
    #pragma unroll
    for (int i = 0; i < 64; i++) acc[i] = 0.0f;

    for (int ci = 0; ci < 16; ci++) {
        const int buf = ci & 3;
        const int par = (ci >> 2) & 1;

        // A fragments don't depend on streamed buffer: load before the wait
        const uint32_t koff = (uint32_t)ci * 512;
        uint32_t ah0[4], ah1[4];
        ldsm4(aB0 + koff, ah0);
        ldsm4(aB1 + koff, ah1);

        MBARRIER_WAIT_PARITY(mbF + 8 * buf, par);

        const uint32_t bBase = uWB + (uint32_t)buf * 8192 + (uint32_t)(nw * 4) * 512 + (uint32_t)lane * 16;
        uint32_t bh[16];
        #pragma unroll
        for (int g = 0; g < 4; g++) ldsm4(bBase + g * 512, bh + 4 * g);

        #pragma unroll
        for (int g = 0; g < 4; g++) {
            mma16816(&acc[g * 16 + 0],  ah0, bh[4 * g + 0], bh[4 * g + 1]);
            mma16816(&acc[g * 16 + 4],  ah0, bh[4 * g + 2], bh[4 * g + 3]);
            mma16816(&acc[g * 16 + 8],  ah1, bh[4 * g + 0], bh[4 * g + 1]);
            mma16816(&acc[g * 16 + 12], ah1, bh[4 * g + 2], bh[4 * g + 3]);
        }

        if (lane == 0) MBARRIER_ARRIVE(mbC + 8 * buf);
        if (tid == 0 && ci + 4 < 32) {
            MBARRIER_WAIT_PARITY(mbC + 8 * buf, par);
            const int nx = ci + 4;
            const uint32_t sz = (nx < 16) ? 8192u : 4096u;
            const unsigned char* src = (nx < 16) ? (g_wimg + (size_t)nx * 8192)
                                                 : (g_wimg + IMG3 + (size_t)(nx - 16) * 4096);
            MBARRIER_EXPECT_TX(mbF + 8 * buf, sz);
            bulk_copy(uWB + (uint32_t)buf * 8192, src, sz, mbF + 8 * buf);
        }
    }
    __syncthreads();   // everyone done reading A before overwrite

    // epilogue: silu(acc + b2) -> packed A fp16
    {
        const int rbase = mrow + (lane >> 2);
        const int cbase = 2 * (lane & 3);
        #pragma unroll
        for (int g = 0; g < 4; g++) {
            #pragma unroll
            for (int m2 = 0; m2 < 2; m2++) {
                #pragma unroll
                for (int h = 0; h < 2; h++) {
                    const int idx = g * 16 + m2 * 8 + h * 4;
                    const int col = nw * 64 + g * 16 + h * 8 + cbase;
                    const float2 bb2 = *(const float2*)&b2s[col];
                    float v0 = silu_f(acc[idx + 0] + bb2.x);
                    float v1 = silu_f(acc[idx + 1] + bb2.y);
                    __half2 hh = __floats2half2_rn(v0, v1);
                    *(uint32_t*)(sm + OFF_AHI + a_off(rbase + m2 * 16, col)) =
                        *reinterpret_cast<uint32_t*>(&hh);
                    float v2 = silu_f(acc[idx + 2] + bb2.x);
                    float v3 = silu_f(acc[idx + 3] + bb2.y);
                    hh = __floats2half2_rn(v2, v3);
                    *(uint32_t*)(sm + OFF_AHI + a_off(rbase + m2 * 16 + 8, col)) =
                        *reinterpret_cast<uint32_t*>(&hh);
                }
            }
        }
    }
    __syncthreads();

    // ================= layer 3: C[128,128], warp tile 32x32 =================
    float acc3[32];
    #pragma unroll
    for (int i = 0; i < 32; i++) acc3[i] = 0.0f;

    for (int ci = 16; ci < 32; ci++) {
        const int buf = ci & 3;
        const int par = (ci >> 2) & 1;

        const uint32_t koff = (uint32_t)(ci - 16) * 512;
        uint32_t ah0[4], ah1[4];
        ldsm4(aB0 + koff, ah0);
        ldsm4(aB1 + koff, ah1);

        MBARRIER_WAIT_PARITY(mbF + 8 * buf, par);

        const uint32_t bBase = uWB + (uint32_t)buf * 8192 + (uint32_t)(nw * 2) * 512 + (uint32_t)lane * 16;
        uint32_t bh[8];
        #pragma unroll
        for (int g = 0; g < 2; g++) ldsm4(bBase + g * 512, bh + 4 * g);
        #pragma unroll
        for (int g = 0; g < 2; g++) {
            mma16816(&acc3[g * 16 + 0],  ah0, bh[4 * g + 0], bh[4 * g + 1]);
            mma16816(&acc3[g * 16 + 4],  ah0, bh[4 * g + 2], bh[4 * g + 3]);
            mma16816(&acc3[g * 16 + 8],  ah1, bh[4 * g + 0], bh[4 * g + 1]);
            mma16816(&acc3[g * 16 + 12], ah1, bh[4 * g + 2], bh[4 * g + 3]);
        }

        if (lane == 0) MBARRIER_ARRIVE(mbC + 8 * buf);
        if (tid == 0 && ci + 4 < 32) {
            MBARRIER_WAIT_PARITY(mbC + 8 * buf, par);
            const int nx = ci + 4;
            MBARRIER_EXPECT_TX(mbF + 8 * buf, 4096);
            bulk_copy(uWB + (uint32_t)buf * 8192,
                      g_wimg + IMG3 + (size_t)(nx - 16) * 4096, 4096, mbF + 8 * buf);
        }
    }

    // ---- layer 4 partials from registers: silu(acc3+b3) . W4 ----
    {
        float p[4][3];
        #pragma unroll
        for (int s = 0; s < 4; s++) { p[s][0] = 0.f; p[s][1] = 0.f; p[s][2] = 0.f; }
        const int cb = 2 * (lane & 3);
        #pragma unroll
        for (int g = 0; g < 2; g++) {
            #pragma unroll
            for (int m2 = 0; m2 < 2; m2++) {
                #pragma unroll
                for (int h = 0; h < 2; h++) {
                    const int idx = g * 16 + m2 * 8 + h * 4;
                    const int col = nw * 32 + g * 16 + h * 8 + cb;
                    const float2 bb3 = *(const float2*)&b3s[col];
                    #pragma unroll
                    for (int j = 0; j < 4; j++) {
                        const int c = col + (j & 1);
                        const float v = silu_f(acc3[idx + j] + ((j & 1) ? bb3.y : bb3.x));
                        const int slot = m2 * 2 + (j >> 1);
                        p[slot][0] = fmaf(v, W4s[c],       p[slot][0]);
                        p[slot][1] = fmaf(v, W4s[128 + c], p[slot][1]);
                        p[slot][2] = fmaf(v, W4s[256 + c], p[slot][2]);
                    }
                }
            }
        }
        #pragma unroll
        for (int s = 0; s < 4; s++)
            #pragma unroll
            for (int g = 0; g < 3; g++) {
                p[s][g] += __shfl_xor_sync(0xffffffffu, p[s][g], 1);
                p[s][g] += __shfl_xor_sync(0xffffffffu, p[s][g], 2);
            }
        if ((lane & 3) == 0) {
            const int r = lane >> 2;
            #pragma unroll
            for (int s = 0; s < 4; s++) {
                const int row = mrow + (s >> 1) * 16 + (s & 1) * 8 + r;
                part[row * 12 + nw * 3 + 0] = p[s][0];
                part[row * 12 + nw * 3 + 1] = p[s][1];
                part[row * 12 + nw * 3 + 2] = p[s][2];
            }
        }
    }
    __syncthreads();

    // ---- softmax + store ----
    if (tid < ROWSPB) {
        const int m = tid;
        float l0 = b4s[0], l1 = b4s[1], l2 = b4s[2];
        #pragma unroll
        for (int c = 0; c < 4; c++) {
            l0 += part[m * 12 + c * 3 + 0];
            l1 += part[m * 12 + c * 3 + 1];
            l2 += part[m * 12 + c * 3 + 2];
        }
        l0 *= beta; l1 *= beta; l2 *= beta;
        const float mx = fmaxf(l0, fmaxf(l1, l2));
        const float e0 = __expf(l0 - mx);
        const float e1 = __expf(l1 - mx);
        const float e2 = __expf(l2 - mx);
        const float inv = __frcp_rn(e0 + e1 + e2);
        const int r = row0 + m;
        out[r * 3 + 0] = e0 * inv;
        out[r * 3 + 1] = e1 * inv;
        out[r * 3 + 2] = e2 * inv;
    }
}

extern "C" void kernel_launch(void* const* d_in, const int* in_sizes, int n_in,
                              void* d_out, int out_size)
{
    const float* log_p     = (const float*)d_in[0];
    const float* log_y     = (const float*)d_in[1];
    const float* log_xb    = (const float*)d_in[2];
    const float* log_q     = (const float*)d_in[3];
    const float* W1        = (const float*)d_in[4];
    const float* b1        = (const float*)d_in[5];
    const float* W2        = (const float*)d_in[6];
    const float* b2        = (const float*)d_in[7];
    const float* W3        = (const float*)d_in[8];
    const float* b3        = (const float*)d_in[9];
    const float* W4        = (const float*)d_in[10];
    const float* b4        = (const float*)d_in[11];
    const float* log_beta  = (const float*)d_in[12];
    const float* log_delta = (const float*)d_in[13];
    float* out = (float*)d_out;

    const int B = in_sizes[1];
    const int grid = B / ROWSPB;

    prep_weights<<<96, 1024>>>(W2, W3);

    cudaFuncSetAttribute(mdp_mma_kernel,
                         cudaFuncAttributeMaxDynamicSharedMemorySize, SMEM_BYTES);

    mdp_mma_kernel<<<grid, THREADS, SMEM_BYTES>>>(
        log_p, log_y, log_xb, log_q,
        W1, b1, b2, b3, W4, b4,
        log_beta, log_delta, out);
}

// round 14
// speedup vs baseline: 1.0015x; 1.0011x over previous
#include <cuda_runtime.h>
#include <cuda_fp16.h>
#include <cstdint>

#define THREADS 512
#define ROWSPB  128

// ---- smem byte offsets (from 128-aligned base) ----
#define OFF_AHI  0              // 128x256 fp16 packed blocks: 65536
#define OFF_WB   65536          // 4 buffers x 8192
#define OFF_W1S  98304          // 8192
#define OFF_B1S  106496
#define OFF_B2S  107520
#define OFF_B3S  108544
#define OFF_W4S  109056
#define OFF_B4S  110592
#define OFF_PART 110608         // 128*12 floats = 6144
#define OFF_MB   116752         // full[4] cons[4] = 64
#define SMEM_BYTES (116816 + 256)

// weight image (fp16): W2 = 16 k16-chunks x 8192; W3 at 131072 = 16 x 4096
#define IMG3 131072
__device__ __align__(16) unsigned char g_wimg[131072 + 65536];

// ---------------- helpers ----------------
__device__ __forceinline__ uint32_t smem_u32(const void* p) {
    uint32_t a;
    asm("{ .reg .u64 t; cvta.to.shared.u64 t, %1; cvt.u32.u64 %0, t; }" : "=r"(a) : "l"(p));
    return a;
}

#define MBARRIER_INIT(addr, cnt) \
    asm volatile("mbarrier.init.shared.b64 [%0], %1;" :: "r"((uint32_t)(addr)), "r"((uint32_t)(cnt)) : "memory")
#define MBARRIER_ARRIVE(addr) \
    asm volatile("mbarrier.arrive.shared.b64 _, [%0];" :: "r"((uint32_t)(addr)) : "memory")
#define MBARRIER_EXPECT_TX(addr, bytes) \
    asm volatile("mbarrier.arrive.expect_tx.shared.b64 _, [%0], %1;" :: "r"((uint32_t)(addr)), "r"((uint32_t)(bytes)) : "memory")
#define MBARRIER_WAIT_PARITY(addr, parity) do {                                   \
    uint32_t _mb = (uint32_t)(addr); uint32_t _p = (uint32_t)(parity);            \
    asm volatile(                                                                 \
        "{\n\t.reg .pred P;\n\t"                                                  \
        "WL_%=:\n\t"                                                              \
        "mbarrier.try_wait.parity.acquire.cta.shared::cta.b64 P, [%0], %1, 0x989680;\n\t" \
        "@P bra.uni WD_%=;\n\t"                                                   \
        "bra.uni WL_%=;\n\t"                                                      \
        "WD_%=:\n\t}"                                                             \
        :: "r"(_mb), "r"(_p) : "memory");                                         \
} while (0)
#define FENCE_PROXY_ASYNC() asm volatile("fence.proxy.async.shared::cta;" ::: "memory")

__device__ __forceinline__ void bulk_copy(uint32_t smem_dst, const void* gsrc,
                                          uint32_t bytes, uint32_t mbar) {
    uint64_t g = (uint64_t)__cvta_generic_to_global(gsrc);
    asm volatile(
        "cp.async.bulk.shared::cta.global.mbarrier::complete_tx::bytes [%0], [%1], %2, [%3];"
        :: "r"(smem_dst), "l"(g), "r"(bytes), "r"(mbar) : "memory");
}

__device__ __forceinline__ void ldsm4(uint32_t a, uint32_t* r) {
    asm volatile("ldmatrix.sync.aligned.m8n8.x4.shared.b16 {%0,%1,%2,%3}, [%4];"
        : "=r"(r[0]), "=r"(r[1]), "=r"(r[2]), "=r"(r[3]) : "r"(a));
}

__device__ __forceinline__ void mma16816(float* d, const uint32_t* a, uint32_t b0, uint32_t b1) {
    asm("mma.sync.aligned.m16n8k16.row.col.f32.f16.f16.f32 "
        "{%0,%1,%2,%3}, {%4,%5,%6,%7}, {%8,%9}, {%0,%1,%2,%3};"
        : "+f"(d[0]), "+f"(d[1]), "+f"(d[2]), "+f"(d[3])
        : "r"(a[0]), "r"(a[1]), "r"(a[2]), "r"(a[3]), "r"(b0), "r"(b1));
}

__device__ __forceinline__ float silu_f(float x) {
    return __fdividef(x, 1.0f + __expf(-x));
}

// packed-block byte offset for A: (m,k) in 128x256, blocks 16x16 = 4 contiguous 8x8 tiles
__device__ __forceinline__ uint32_t a_off(int m, int k) {
    return (uint32_t)((m >> 4) * 8192 + (k >> 4) * 512 +
           (((m & 8) >> 3) + ((k & 8) >> 3) * 2) * 128 + (m & 7) * 16 + (k & 7) * 2);
}

// ---------------- prologue: convert + pack weights (fp16) ----------------
__global__ void prep_weights(const float* __restrict__ W2, const float* __restrict__ W3) {
    int idx = blockIdx.x * blockDim.x + threadIdx.x;
    if (idx >= 98304) return;
    float w; size_t off;
    if (idx < 65536) {                   // W2[n][k]
        int n = idx >> 8, k = idx & 255;
        w = W2[idx];
        int u = ((n & 8) >> 3) * 2 + ((k & 8) >> 3);
        off = (size_t)(k >> 4) * 8192 + (size_t)(n >> 4) * 512 + u * 128 + (n & 7) * 16 + (k & 7) * 2;
    } else {                             // W3[n][k], n<128
        int i = idx - 65536;
        int n = i >> 8, k = i & 255;
        w = W3[i];
        int u = ((n & 8) >> 3) * 2 + ((k & 8) >> 3);
        off = IMG3 + (size_t)(k >> 4) * 4096 + (size_t)(n >> 4) * 512 + u * 128 + (n & 7) * 16 + (k & 7) * 2;
    }
    *(__half*)(g_wimg + off) = __float2half_rn(w);
}

// ---------------- main kernel ----------------
extern "C" __global__ void __launch_bounds__(THREADS, 1)
mdp_mma_kernel(const float* __restrict__ log_p,
               const float* __restrict__ log_y,
               const float* __restrict__ log_xb,
               const float* __restrict__ log_q,
               const float* __restrict__ W1, const float* __restrict__ b1,
               const float* __restrict__ b2, const float* __restrict__ b3,
               const float* __restrict__ W4, const float* __restrict__ b4,
               const float* __restrict__ log_beta,
               const float* __restrict__ log_delta,
               float* __restrict__ out)
{
    extern __shared__ unsigned char dynsm[];
    const uint32_t raw = smem_u32(dynsm);
    const uint32_t abase = (raw + 127u) & ~127u;
    unsigned char* sm = dynsm + (abase - raw);

    float* W1s = (float*)(sm + OFF_W1S);
    float* b1s = (float*)(sm + OFF_B1S);
    float* b2s = (float*)(sm + OFF_B2S);
    float* b3s = (float*)(sm + OFF_B3S);
    float* W4s = (float*)(sm + OFF_W4S);
    float* b4s = (float*)(sm + OFF_B4S);
    float* part = (float*)(sm + OFF_PART);

    const uint32_t uAH = abase + OFF_AHI;
    const uint32_t uWB = abase + OFF_WB;
    const uint32_t mbF = abase + OFF_MB;        // full[i] at +8*i
    const uint32_t mbC = abase + OFF_MB + 32;   // cons[i] at +8*i

    const int tid  = threadIdx.x;
    const int wid  = tid >> 5;
    const int lane = tid & 31;
    const int row0 = blockIdx.x * ROWSPB;

    const float delta = 1.0f / (1.0f + __expf(-log_delta[0]));
    float beta = __expf(log_beta[0]);
    beta = fminf(fmaxf(beta, 0.5f), 20.0f);

    // init barriers + kick off first 4 chunk loads
    if (tid == 0) {
        #pragma unroll
        for (int i = 0; i < 4; i++) {
            MBARRIER_INIT(mbF + 8 * i, 1);
            MBARRIER_INIT(mbC + 8 * i, 16);
        }
        FENCE_PROXY_ASYNC();
        #pragma unroll
        for (int i = 0; i < 4; i++) {
            MBARRIER_EXPECT_TX(mbF + 8 * i, 8192);
            bulk_copy(uWB + i * 8192, g_wimg + (size_t)i * 8192, 8192, mbF + 8 * i);
        }
    }

    // stage small params
    for (int i = tid; i < 2048; i += THREADS) {
        const int k = i >> 3, c = i & 7;
        W1s[i] = (c < 7) ? W1[k * 7 + c] : 0.0f;
    }
    if (tid < 256) { b1s[tid] = b1[tid]; b2s[tid] = b2[tid]; }
    if (tid < 128) b3s[tid] = b3[tid];
    if (tid < 384) W4s[tid] = W4[tid];
    if (tid < 3)   b4s[tid] = b4[tid];
    __syncthreads();

    // ---- layer 1 (fp32 exact) -> packed A fp16 ----
    {
        const int m  = tid & 127;
        const int k0 = (tid >> 7) * 64;
        const int r  = row0 + m;
        float x0 = log_p[r * 3 + 0], x1 = log_p[r * 3 + 1], x2 = log_p[r * 3 + 2];
        float x3 = log_y[r];
        float x4 = delta * log_xb[r * 3 + 0] + (1.0f - delta) * log_q[r * 3 + 0];
        float x5 = delta * log_xb[r * 3 + 1] + (1.0f - delta) * log_q[r * 3 + 1];
        float x6 = delta * log_xb[r * 3 + 2] + (1.0f - delta) * log_q[r * 3 + 2];
        #pragma unroll 8
        for (int j = 0; j < 64; j += 2) {
            const int k = k0 + j;
            const float4 w0 = *(const float4*)&W1s[k * 8];
            const float4 w1 = *(const float4*)&W1s[k * 8 + 4];
            const float4 u0 = *(const float4*)&W1s[(k + 1) * 8];
            const float4 u1 = *(const float4*)&W1s[(k + 1) * 8 + 4];
            const float2 bb = *(const float2*)&b1s[k];
            float v0 = bb.x, v1 = bb.y;
            v0 = fmaf(x0, w0.x, v0); v1 = fmaf(x0, u0.x, v1);
            v0 = fmaf(x1, w0.y, v0); v1 = fmaf(x1, u0.y, v1);
            v0 = fmaf(x2, w0.z, v0); v1 = fmaf(x2, u0.z, v1);
            v0 = fmaf(x3, w0.w, v0); v1 = fmaf(x3, u0.w, v1);
            v0 = fmaf(x4, w1.x, v0); v1 = fmaf(x4, u1.x, v1);
            v0 = fmaf(x5, w1.y, v0); v1 = fmaf(x5, u1.y, v1);
            v0 = fmaf(x6, w1.z, v0); v1 = fmaf(x6, u1.z, v1);
            v0 = silu_f(v0); v1 = silu_f(v1);
            __half2 h = __floats2half2_rn(v0, v1);
            *(uint32_t*)(sm + OFF_AHI + a_off(m, k)) = *reinterpret_cast<uint32_t*>(&h);
        }
    }
    __syncthreads();

    // warp tiling: 4m x 4n
    const int mw = wid & 3;
    const int nw = wid >> 2;
    const int mrow = mw * 32;
    const uint32_t aB0 = uAH + (uint32_t)(mw * 2) * 8192 + (uint32_t)lane * 16;
    const uint32_t aB1 = aB0 + 8192;

    // ================= layer 2: C[128,256], warp tile 32x64 =================
    float acc[64];
    #pragma unroll
    for (int i = 0; i < 64; i++) acc[i] = 0.0f;

    for (int ci = 0; ci < 16; ci++) {
        const int buf = ci & 3;
        const int par = (ci >> 2) & 1;

        // A fragments don't depend on streamed buffer: load before the wait
        const uint32_t koff = (uint32_t)ci * 512;
        uint32_t ah0[4], ah1[4];
        ldsm4(aB0 + koff, ah0);
        ldsm4(aB1 + koff, ah1);

        MBARRIER_WAIT_PARITY(mbF + 8 * buf, par);

        const uint32_t bBase = uWB + (uint32_t)buf * 8192 + (uint32_t)(nw * 4) * 512 + (uint32_t)lane * 16;
        uint32_t bh[16];
        #pragma unroll
        for (int g = 0; g < 4; g++) ldsm4(bBase + g * 512, bh + 4 * g);

        #pragma unroll
        for (int g = 0; g < 4; g++) {
            mma16816(&acc[g * 16 + 0],  ah0, bh[4 * g + 0], bh[4 * g + 1]);
            mma16816(&acc[g * 16 + 4],  ah0, bh[4 * g + 2], bh[4 * g + 3]);
            mma16816(&acc[g * 16 + 8],  ah1, bh[4 * g + 0], bh[4 * g + 1]);
            mma16816(&acc[g * 16 + 12], ah1, bh[4 * g + 2], bh[4 * g + 3]);
        }

        if (lane == 0) MBARRIER_ARRIVE(mbC + 8 * buf);
        if (tid == 0 && ci + 4 < 32) {
            MBARRIER_WAIT_PARITY(mbC + 8 * buf, par);
            const int nx = ci + 4;
            const uint32_t sz = (nx < 16) ? 8192u : 4096u;
            const unsigned char* src = (nx < 16) ? (g_wimg + (size_t)nx * 8192)
                                                 : (g_wimg + IMG3 + (size_t)(nx - 16) * 4096);
            MBARRIER_EXPECT_TX(mbF + 8 * buf, sz);
            bulk_copy(uWB + (uint32_t)buf * 8192, src, sz, mbF + 8 * buf);
        }
    }
    __syncthreads();   // everyone done reading A before overwrite

    // epilogue: silu(acc + b2) -> packed A fp16
    {
        const int rbase = mrow + (lane >> 2);
        const int cbase = 2 * (lane & 3);
        #pragma unroll
        for (int g = 0; g < 4; g++) {
            #pragma unroll
            for (int m2 = 0; m2 < 2; m2++) {
                #pragma unroll
                for (int h = 0; h < 2; h++) {
                    const int idx = g * 16 + m2 * 8 + h * 4;
                    const int col = nw * 64 + g * 16 + h * 8 + cbase;
                    const float2 bb2 = *(const float2*)&b2s[col];
                    float v0 = silu_f(acc[idx + 0] + bb2.x);
                    float v1 = silu_f(acc[idx + 1] + bb2.y);
                    __half2 hh = __floats2half2_rn(v0, v1);
                    *(uint32_t*)(sm + OFF_AHI + a_off(rbase + m2 * 16, col)) =
                        *reinterpret_cast<uint32_t*>(&hh);
                    float v2 = silu_f(acc[idx + 2] + bb2.x);
                    float v3 = silu_f(acc[idx + 3] + bb2.y);
                    hh = __floats2half2_rn(v2, v3);
                    *(uint32_t*)(sm + OFF_AHI + a_off(rbase + m2 * 16 + 8, col)) =
                        *reinterpret_cast<uint32_t*>(&hh);
                }
            }
        }
    }
    __syncthreads();

    // ================= layer 3: C[128,128], warp tile 32x32 =================
    float acc3[32];
    #pragma unroll
    for (int i = 0; i < 32; i++) acc3[i] = 0.0f;

    for (int ci = 16; ci < 32; ci++) {
        const int buf = ci & 3;
        const int par = (ci >> 2) & 1;

        const uint32_t koff = (uint32_t)(ci - 16) * 512;
        uint32_t ah0[4], ah1[4];
        ldsm4(aB0 + koff, ah0);
        ldsm4(aB1 + koff, ah1);

        MBARRIER_WAIT_PARITY(mbF + 8 * buf, par);

        const uint32_t bBase = uWB + (uint32_t)buf * 8192 + (uint32_t)(nw * 2) * 512 + (uint32_t)lane * 16;
        uint32_t bh[8];
        #pragma unroll
        for (int g = 0; g < 2; g++) ldsm4(bBase + g * 512, bh + 4 * g);
        #pragma unroll
        for (int g = 0; g < 2; g++) {
            mma16816(&acc3[g * 16 + 0],  ah0, bh[4 * g + 0], bh[4 * g + 1]);
            mma16816(&acc3[g * 16 + 4],  ah0, bh[4 * g + 2], bh[4 * g + 3]);
            mma16816(&acc3[g * 16 + 8],  ah1, bh[4 * g + 0], bh[4 * g + 1]);
            mma16816(&acc3[g * 16 + 12], ah1, bh[4 * g + 2], bh[4 * g + 3]);
        }

        if (lane == 0) MBARRIER_ARRIVE(mbC + 8 * buf);
        if (tid == 0 && ci + 4 < 32) {
            MBARRIER_WAIT_PARITY(mbC + 8 * buf, par);
            const int nx = ci + 4;
            MBARRIER_EXPECT_TX(mbF + 8 * buf, 4096);
            bulk_copy(uWB + (uint32_t)buf * 8192,
                      g_wimg + IMG3 + (size_t)(nx - 16) * 4096, 4096, mbF + 8 * buf);
        }
    }

    // ---- layer 4 partials from registers: silu(acc3+b3) . W4 ----
    {
        float p[4][3];
        #pragma unroll
        for (int s = 0; s < 4; s++) { p[s][0] = 0.f; p[s][1] = 0.f; p[s][2] = 0.f; }
        const int cb = 2 * (lane & 3);
        #pragma unroll
        for (int g = 0; g < 2; g++) {
            #pragma unroll
            for (int m2 = 0; m2 < 2; m2++) {
                #pragma unroll
                for (int h = 0; h < 2; h++) {
                    const int idx = g * 16 + m2 * 8 + h * 4;
                    const int col = nw * 32 + g * 16 + h * 8 + cb;
                    const float2 bb3 = *(const float2*)&b3s[col];
                    #pragma unroll
                    for (int j = 0; j < 4; j++) {
                        const int c = col + (j & 1);
                        const float v = silu_f(acc3[idx + j] + ((j & 1) ? bb3.y : bb3.x));
                        const int slot = m2 * 2 + (j >> 1);
                        p[slot][0] = fmaf(v, W4s[c],       p[slot][0]);
                        p[slot][1] = fmaf(v, W4s[128 + c], p[slot][1]);
                        p[slot][2] = fmaf(v, W4s[256 + c], p[slot][2]);
                    }
                }
            }
        }
        #pragma unroll
        for (int s = 0; s < 4; s++)
            #pragma unroll
            for (int g = 0; g < 3; g++) {
                p[s][g] += __shfl_xor_sync(0xffffffffu, p[s][g], 1);
                p[s][g] += __shfl_xor_sync(0xffffffffu, p[s][g], 2);
            }
        if ((lane & 3) == 0) {
            const int r = lane >> 2;
            #pragma unroll
            for (int s = 0; s < 4; s++) {
                const int row = mrow + (s >> 1) * 16 + (s & 1) * 8 + r;
                part[row * 12 + nw * 3 + 0] = p[s][0];
                part[row * 12 + nw * 3 + 1] = p[s][1];
                part[row * 12 + nw * 3 + 2] = p[s][2];
            }
        }
    }
    __syncthreads();

    // ---- softmax + store ----
    if (tid < ROWSPB) {
        const int m = tid;
        float l0 = b4s[0], l1 = b4s[1], l2 = b4s[2];
        #pragma unroll
        for (int c = 0; c < 4; c++) {
            l0 += part[m * 12 + c * 3 + 0];
            l1 += part[m * 12 + c * 3 + 1];
            l2 += part[m * 12 + c * 3 + 2];
        }
        l0 *= beta; l1 *= beta; l2 *= beta;
        const float mx = fmaxf(l0, fmaxf(l1, l2));
        const float e0 = __expf(l0 - mx);
        const float e1 = __expf(l1 - mx);
        const float e2 = __expf(l2 - mx);
        const float inv = __frcp_rn(e0 + e1 + e2);
        const int r = row0 + m;
        out[r * 3 + 0] = e0 * inv;
        out[r * 3 + 1] = e1 * inv;
        out[r * 3 + 2] = e2 * inv;
    }
}

extern "C" void kernel_launch(void* const* d_in, const int* in_sizes, int n_in,
                              void* d_out, int out_size)
{
    const float* log_p     = (const float*)d_in[0];
    const float* log_y     = (const float*)d_in[1];
    const float* log_xb    = (const float*)d_in[2];
    const float* log_q     = (const float*)d_in[3];
    const float* W1        = (const float*)d_in[4];
    const float* b1        = (const float*)d_in[5];
    const float* W2        = (const float*)d_in[6];
    const float* b2        = (const float*)d_in[7];
    const float* W3        = (const float*)d_in[8];
    const float* b3        = (const float*)d_in[9];
    const float* W4        = (const float*)d_in[10];
    const float* b4        = (const float*)d_in[11];
    const float* log_beta  = (const float*)d_in[12];
    const float* log_delta = (const float*)d_in[13];
    float* out = (float*)d_out;

    const int B = in_sizes[1];
    const int grid = B / ROWSPB;

    prep_weights<<<96, 1024>>>(W2, W3);

    cudaFuncSetAttribute(mdp_mma_kernel,
                         cudaFuncAttributeMaxDynamicSharedMemorySize, SMEM_BYTES);

    mdp_mma_kernel<<<grid, THREADS, SMEM_BYTES>>>(
        log_p, log_y, log_xb, log_q,
        W1, b1, b2, b3, W4, b4,
        log_beta, log_delta, out);
}

// round 15
// speedup vs baseline: 1.0027x; 1.0012x over previous
#include <cuda_runtime.h>
#include <cuda_fp16.h>
#include <cstdint>

#define THREADS 512
#define ROWSPB  128

// ---- smem byte offsets (from 128-aligned base) ----
#define OFF_AHI  0              // 128x256 fp16 packed blocks: 65536
#define OFF_WB   65536          // 4 buffers x 8192
#define OFF_W1S  98304          // 8192
#define OFF_B1S  106496
#define OFF_B2S  107520
#define OFF_B3S  108544
#define OFF_W4S  109056
#define OFF_B4S  110592
#define OFF_PART 110608         // 128*12 floats = 6144
#define OFF_MB   116752         // full[4] cons[4] = 64
#define SMEM_BYTES (116816 + 256)

// weight image (fp16): W2 = 16 k16-chunks x 8192; W3 at 131072 = 16 x 4096
#define IMG3 131072
__device__ __align__(16) unsigned char g_wimg[131072 + 65536];

// ---------------- helpers ----------------
__device__ __forceinline__ uint32_t smem_u32(const void* p) {
    uint32_t a;
    asm("{ .reg .u64 t; cvta.to.shared.u64 t, %1; cvt.u32.u64 %0, t; }" : "=r"(a) : "l"(p));
    return a;
}

#define MBARRIER_INIT(addr, cnt) \
    asm volatile("mbarrier.init.shared.b64 [%0], %1;" :: "r"((uint32_t)(addr)), "r"((uint32_t)(cnt)) : "memory")
#define MBARRIER_ARRIVE(addr) \
    asm volatile("mbarrier.arrive.shared.b64 _, [%0];" :: "r"((uint32_t)(addr)) : "memory")
#define MBARRIER_EXPECT_TX(addr, bytes) \
    asm volatile("mbarrier.arrive.expect_tx.shared.b64 _, [%0], %1;" :: "r"((uint32_t)(addr)), "r"((uint32_t)(bytes)) : "memory")
#define MBARRIER_WAIT_PARITY(addr, parity) do {                                   \
    uint32_t _mb = (uint32_t)(addr); uint32_t _p = (uint32_t)(parity);            \
    asm volatile(                                                                 \
        "{\n\t.reg .pred P;\n\t"                                                  \
        "WL_%=:\n\t"                                                              \
        "mbarrier.try_wait.parity.acquire.cta.shared::cta.b64 P, [%0], %1, 0x989680;\n\t" \
        "@P bra.uni WD_%=;\n\t"                                                   \
        "bra.uni WL_%=;\n\t"                                                      \
        "WD_%=:\n\t}"                                                             \
        :: "r"(_mb), "r"(_p) : "memory");                                         \
} while (0)
#define FENCE_PROXY_ASYNC() asm volatile("fence.proxy.async.shared::cta;" ::: "memory")

__device__ __forceinline__ void bulk_copy(uint32_t smem_dst, const void* gsrc,
                                          uint32_t bytes, uint32_t mbar) {
    uint64_t g = (uint64_t)__cvta_generic_to_global(gsrc);
    asm volatile(
        "cp.async.bulk.shared::cta.global.mbarrier::complete_tx::bytes [%0], [%1], %2, [%3];"
        :: "r"(smem_dst), "l"(g), "r"(bytes), "r"(mbar) : "memory");
}

__device__ __forceinline__ void ldsm4(uint32_t a, uint32_t* r) {
    asm volatile("ldmatrix.sync.aligned.m8n8.x4.shared.b16 {%0,%1,%2,%3}, [%4];"
        : "=r"(r[0]), "=r"(r[1]), "=r"(r[2]), "=r"(r[3]) : "r"(a));
}

__device__ __forceinline__ void mma16816(float* d, const uint32_t* a, uint32_t b0, uint32_t b1) {
    asm("mma.sync.aligned.m16n8k16.row.col.f32.f16.f16.f32 "
        "{%0,%1,%2,%3}, {%4,%5,%6,%7}, {%8,%9}, {%0,%1,%2,%3};"
        : "+f"(d[0]), "+f"(d[1]), "+f"(d[2]), "+f"(d[3])
        : "r"(a[0]), "r"(a[1]), "r"(a[2]), "r"(a[3]), "r"(b0), "r"(b1));
}

__device__ __forceinline__ float silu_f(float x) {
    return __fdividef(x, 1.0f + __expf(-x));
}

// packed-block byte offset for A: (m,k) in 128x256, blocks 16x16 = 4 contiguous 8x8 tiles
__device__ __forceinline__ uint32_t a_off(int m, int k) {
    return (uint32_t)((m >> 4) * 8192 + (k >> 4) * 512 +
           (((m & 8) >> 3) + ((k & 8) >> 3) * 2) * 128 + (m & 7) * 16 + (k & 7) * 2);
}

// ---------------- prologue: convert + pack weights (fp16) ----------------
__global__ void prep_weights(const float* __restrict__ W2, const float* __restrict__ W3) {
    int idx = blockIdx.x * blockDim.x + threadIdx.x;
    if (idx >= 98304) return;
    float w; size_t off;
    if (idx < 65536) {                   // W2[n][k]
        int n = idx >> 8, k = idx & 255;
        w = W2[idx];
        int u = ((n & 8) >> 3) * 2 + ((k & 8) >> 3);
        off = (size_t)(k >> 4) * 8192 + (size_t)(n >> 4) * 512 + u * 128 + (n & 7) * 16 + (k & 7) * 2;
    } else {                             // W3[n][k], n<128
        int i = idx - 65536;
        int n = i >> 8, k = i & 255;
        w = W3[i];
        int u = ((n & 8) >> 3) * 2 + ((k & 8) >> 3);
        off = IMG3 + (size_t)(k >> 4) * 4096 + (size_t)(n >> 4) * 512 + u * 128 + (n & 7) * 16 + (k & 7) * 2;
    }
    *(__half*)(g_wimg + off) = __float2half_rn(w);
}

// ---------------- main kernel ----------------
extern "C" __global__ void __launch_bounds__(THREADS, 1)
mdp_mma_kernel(const float* __restrict__ log_p,
               const float* __restrict__ log_y,
               const float* __restrict__ log_xb,
               const float* __restrict__ log_q,
               const float* __restrict__ W1, const float* __restrict__ b1,
               const float* __restrict__ b2, const float* __restrict__ b3,
               const float* __restrict__ W4, const float* __restrict__ b4,
               const float* __restrict__ log_beta,
               const float* __restrict__ log_delta,
               float* __restrict__ out)
{
    extern __shared__ unsigned char dynsm[];
    const uint32_t raw = smem_u32(dynsm);
    const uint32_t abase = (raw + 127u) & ~127u;
    unsigned char* sm = dynsm + (abase - raw);

    float* W1s = (float*)(sm + OFF_W1S);
    float* b1s = (float*)(sm + OFF_B1S);
    float* b2s = (float*)(sm + OFF_B2S);
    float* b3s = (float*)(sm + OFF_B3S);
    float* W4s = (float*)(sm + OFF_W4S);
    float* b4s = (float*)(sm + OFF_B4S);
    float* part = (float*)(sm + OFF_PART);

    const uint32_t uAH = abase + OFF_AHI;
    const uint32_t uWB = abase + OFF_WB;
    const uint32_t mbF = abase + OFF_MB;        // full[i] at +8*i
    const uint32_t mbC = abase + OFF_MB + 32;   // cons[i] at +8*i

    const int tid  = threadIdx.x;
    const int wid  = tid >> 5;
    const int lane = tid & 31;
    const int row0 = blockIdx.x * ROWSPB;

    const float delta = 1.0f / (1.0f + __expf(-log_delta[0]));
    float beta = __expf(log_beta[0]);
    beta = fminf(fmaxf(beta, 0.5f), 20.0f);

    // init barriers + kick off first 4 chunk loads
    if (tid == 0) {
        #pragma unroll
        for (int i = 0; i < 4; i++) {
            MBARRIER_INIT(mbF + 8 * i, 1);
            MBARRIER_INIT(mbC + 8 * i, 16);
        }
        FENCE_PROXY_ASYNC();
        #pragma unroll
        for (int i = 0; i < 4; i++) {
            MBARRIER_EXPECT_TX(mbF + 8 * i, 8192);
            bulk_copy(uWB + i * 8192, g_wimg + (size_t)i * 8192, 8192, mbF + 8 * i);
        }
    }

    // stage small params
    for (int i = tid; i < 2048; i += THREADS) {
        const int k = i >> 3, c = i & 7;
        W1s[i] = (c < 7) ? W1[k * 7 + c] : 0.0f;
    }
    if (tid < 256) { b1s[tid] = b1[tid]; b2s[tid] = b2[tid]; }
    if (tid < 128) b3s[tid] = b3[tid];
    if (tid < 384) W4s[tid] = W4[tid];
    if (tid < 3)   b4s[tid] = b4[tid];
    __syncthreads();

    // ---- layer 1 (fp32 exact) -> packed A fp16 ----
    {
        const int m  = tid & 127;
        const int k0 = (tid >> 7) * 64;
        const int r  = row0 + m;
        float x0 = log_p[r * 3 + 0], x1 = log_p[r * 3 + 1], x2 = log_p[r * 3 + 2];
        float x3 = log_y[r];
        float x4 = delta * log_xb[r * 3 + 0] + (1.0f - delta) * log_q[r * 3 + 0];
        float x5 = delta * log_xb[r * 3 + 1] + (1.0f - delta) * log_q[r * 3 + 1];
        float x6 = delta * log_xb[r * 3 + 2] + (1.0f - delta) * log_q[r * 3 + 2];
        #pragma unroll 8
        for (int j = 0; j < 64; j += 2) {
            const int k = k0 + j;
            const float4 w0 = *(const float4*)&W1s[k * 8];
            const float4 w1 = *(const float4*)&W1s[k * 8 + 4];
            const float4 u0 = *(const float4*)&W1s[(k + 1) * 8];
            const float4 u1 = *(const float4*)&W1s[(k + 1) * 8 + 4];
            const float2 bb = *(const float2*)&b1s[k];
            float v0 = bb.x, v1 = bb.y;
            v0 = fmaf(x0, w0.x, v0); v1 = fmaf(x0, u0.x, v1);
            v0 = fmaf(x1, w0.y, v0); v1 = fmaf(x1, u0.y, v1);
            v0 = fmaf(x2, w0.z, v0); v1 = fmaf(x2, u0.z, v1);
            v0 = fmaf(x3, w0.w, v0); v1 = fmaf(x3, u0.w, v1);
            v0 = fmaf(x4, w1.x, v0); v1 = fmaf(x4, u1.x, v1);
            v0 = fmaf(x5, w1.y, v0); v1 = fmaf(x5, u1.y, v1);
            v0 = fmaf(x6, w1.z, v0); v1 = fmaf(x6, u1.z, v1);
            v0 = silu_f(v0); v1 = silu_f(v1);
            __half2 h = __floats2half2_rn(v0, v1);
            *(uint32_t*)(sm + OFF_AHI + a_off(m, k)) = *reinterpret_cast<uint32_t*>(&h);
        }
    }
    __syncthreads();

    // warp tiling: 4m x 4n
    const int mw = wid & 3;
    const int nw = wid >> 2;
    const int mrow = mw * 32;
    const uint32_t aB0 = uAH + (uint32_t)(mw * 2) * 8192 + (uint32_t)lane * 16;
    const uint32_t aB1 = aB0 + 8192;

    // ================= layer 2: C[128,256], warp tile 32x64 =================
    float acc[64];
    #pragma unroll
    for (int i = 0; i < 64; i++) acc[i] = 0.0f;

    for (int ci = 0; ci < 16; ci++) {
        const int buf = ci & 3;
        const int par = (ci >> 2) & 1;

        // A fragments don't depend on streamed buffer: load before the wait
        const uint32_t koff = (uint32_t)ci * 512;
        uint32_t ah0[4], ah1[4];
        ldsm4(aB0 + koff, ah0);
        ldsm4(aB1 + koff, ah1);

        MBARRIER_WAIT_PARITY(mbF + 8 * buf, par);

        const uint32_t bBase = uWB + (uint32_t)buf * 8192 + (uint32_t)(nw * 4) * 512 + (uint32_t)lane * 16;
        uint32_t bh[16];
        #pragma unroll
        for (int g = 0; g < 4; g++) ldsm4(bBase + g * 512, bh + 4 * g);

        #pragma unroll
        for (int g = 0; g < 4; g++) {
            mma16816(&acc[g * 16 + 0],  ah0, bh[4 * g + 0], bh[4 * g + 1]);
            mma16816(&acc[g * 16 + 4],  ah0, bh[4 * g + 2], bh[4 * g + 3]);
            mma16816(&acc[g * 16 + 8],  ah1, bh[4 * g + 0], bh[4 * g + 1]);
            mma16816(&acc[g * 16 + 12], ah1, bh[4 * g + 2], bh[4 * g + 3]);
        }

        if (lane == 0) MBARRIER_ARRIVE(mbC + 8 * buf);
        if (tid == 0 && ci + 4 < 32) {
            MBARRIER_WAIT_PARITY(mbC + 8 * buf, par);
            const int nx = ci + 4;
            const uint32_t sz = (nx < 16) ? 8192u : 4096u;
            const unsigned char* src = (nx < 16) ? (g_wimg + (size_t)nx * 8192)
                                                 : (g_wimg + IMG3 + (size_t)(nx - 16) * 4096);
            MBARRIER_EXPECT_TX(mbF + 8 * buf, sz);
            bulk_copy(uWB + (uint32_t)buf * 8192, src, sz, mbF + 8 * buf);
        }
    }
    __syncthreads();   // everyone done reading A before overwrite

    // epilogue: silu(acc + b2) -> packed A fp16
    {
        const int rbase = mrow + (lane >> 2);
        const int cbase = 2 * (lane & 3);
        #pragma unroll
        for (int g = 0; g < 4; g++) {
            #pragma unroll
            for (int m2 = 0; m2 < 2; m2++) {
                #pragma unroll
                for (int h = 0; h < 2; h++) {
                    const int idx = g * 16 + m2 * 8 + h * 4;
                    const int col = nw * 64 + g * 16 + h * 8 + cbase;
                    const float2 bb2 = *(const float2*)&b2s[col];
                    float v0 = silu_f(acc[idx + 0] + bb2.x);
                    float v1 = silu_f(acc[idx + 1] + bb2.y);
                    __half2 hh = __floats2half2_rn(v0, v1);
                    *(uint32_t*)(sm + OFF_AHI + a_off(rbase + m2 * 16, col)) =
                        *reinterpret_cast<uint32_t*>(&hh);
                    float v2 = silu_f(acc[idx + 2] + bb2.x);
                    float v3 = silu_f(acc[idx + 3] + bb2.y);
                    hh = __floats2half2_rn(v2, v3);
                    *(uint32_t*)(sm + OFF_AHI + a_off(rbase + m2 * 16 + 8, col)) =
                        *reinterpret_cast<uint32_t*>(&hh);
                }
            }
        }
    }
    __syncthreads();

    // ================= layer 3: C[128,128], warp tile 32x32 =================
    float acc3[32];
    #pragma unroll
    for (int i = 0; i < 32; i++) acc3[i] = 0.0f;

    for (int ci = 16; ci < 32; ci++) {
        const int buf = ci & 3;
        const int par = (ci >> 2) & 1;

        const uint32_t koff = (uint32_t)(ci - 16) * 512;
        uint32_t ah0[4], ah1[4];
        ldsm4(aB0 + koff, ah0);
        ldsm4(aB1 + koff, ah1);

        MBARRIER_WAIT_PARITY(mbF + 8 * buf, par);

        const uint32_t bBase = uWB + (uint32_t)buf * 8192 + (uint32_t)(nw * 2) * 512 + (uint32_t)lane * 16;
        uint32_t bh[8];
        #pragma unroll
        for (int g = 0; g < 2; g++) ldsm4(bBase + g * 512, bh + 4 * g);
        #pragma unroll
        for (int g = 0; g < 2; g++) {
            mma16816(&acc3[g * 16 + 0],  ah0, bh[4 * g + 0], bh[4 * g + 1]);
            mma16816(&acc3[g * 16 + 4],  ah0, bh[4 * g + 2], bh[4 * g + 3]);
            mma16816(&acc3[g * 16 + 8],  ah1, bh[4 * g + 0], bh[4 * g + 1]);
            mma16816(&acc3[g * 16 + 12], ah1, bh[4 * g + 2], bh[4 * g + 3]);
        }

        if (lane == 0) MBARRIER_ARRIVE(mbC + 8 * buf);
        if (tid == 0 && ci + 4 < 32) {
            MBARRIER_WAIT_PARITY(mbC + 8 * buf, par);
            const int nx = ci + 4;
            MBARRIER_EXPECT_TX(mbF + 8 * buf, 4096);
            bulk_copy(uWB + (uint32_t)buf * 8192,
                      g_wimg + IMG3 + (size_t)(nx - 16) * 4096, 4096, mbF + 8 * buf);
        }
    }

    // ---- layer 4 partials from registers: silu(acc3+b3) . W4 ----
    {
        float p[4][3];
        #pragma unroll
        for (int s = 0; s < 4; s++) { p[s][0] = 0.f; p[s][1] = 0.f; p[s][2] = 0.f; }
        const int cb = 2 * (lane & 3);
        #pragma unroll
        for (int g = 0; g < 2; g++) {
            #pragma unroll
            for (int m2 = 0; m2 < 2; m2++) {
                #pragma unroll
                for (int h = 0; h < 2; h++) {
                    const int idx = g * 16 + m2 * 8 + h * 4;
                    const int col = nw * 32 + g * 16 + h * 8 + cb;
                    const float2 bb3 = *(const float2*)&b3s[col];
                    #pragma unroll
                    for (int j = 0; j < 4; j++) {
                        const int c = col + (j & 1);
                        const float v = silu_f(acc3[idx + j] + ((j & 1) ? bb3.y : bb3.x));
                        const int slot = m2 * 2 + (j >> 1);
                        p[slot][0] = fmaf(v, W4s[c],       p[slot][0]);
                        p[slot][1] = fmaf(v, W4s[128 + c], p[slot][1]);
                        p[slot][2] = fmaf(v, W4s[256 + c], p[slot][2]);
                    }
                }
            }
        }
        #pragma unroll
        for (int s = 0; s < 4; s++)
            #pragma unroll
            for (int g = 0; g < 3; g++) {
                p[s][g] += __shfl_xor_sync(0xffffffffu, p[s][g], 1);
                p[s][g] += __shfl_xor_sync(0xffffffffu, p[s][g], 2);
            }
        if ((lane & 3) == 0) {
            const int r = lane >> 2;
            #pragma unroll
            for (int s = 0; s < 4; s++) {
                const int row = mrow + (s >> 1) * 16 + (s & 1) * 8 + r;
                part[row * 12 + nw * 3 + 0] = p[s][0];
                part[row * 12 + nw * 3 + 1] = p[s][1];
                part[row * 12 + nw * 3 + 2] = p[s][2];
            }
        }
    }
    __syncthreads();

    // ---- softmax + store ----
    if (tid < ROWSPB) {
        const int m = tid;
        float l0 = b4s[0], l1 = b4s[1], l2 = b4s[2];
        #pragma unroll
        for (int c = 0; c < 4; c++) {
            l0 += part[m * 12 + c * 3 + 0];
            l1 += part[m * 12 + c * 3 + 1];
            l2 += part[m * 12 + c * 3 + 2];
        }
        l0 *= beta; l1 *= beta; l2 *= beta;
        const float mx = fmaxf(l0, fmaxf(l1, l2));
        const float e0 = __expf(l0 - mx);
        const float e1 = __expf(l1 - mx);
        const float e2 = __expf(l2 - mx);
        const float inv = __frcp_rn(e0 + e1 + e2);
        const int r = row0 + m;
        out[r * 3 + 0] = e0 * inv;
        out[r * 3 + 1] = e1 * inv;
        out[r * 3 + 2] = e2 * inv;
    }
}

extern "C" void kernel_launch(void* const* d_in, const int* in_sizes, int n_in,
                              void* d_out, int out_size)
{
    const float* log_p     = (const float*)d_in[0];
    const float* log_y     = (const float*)d_in[1];
    const float* log_xb    = (const float*)d_in[2];
    const float* log_q     = (const float*)d_in[3];
    const float* W1        = (const float*)d_in[4];
    const float* b1        = (const float*)d_in[5];
    const float* W2        = (const float*)d_in[6];
    const float* b2        = (const float*)d_in[7];
    const float* W3        = (const float*)d_in[8];
    const float* b3        = (const float*)d_in[9];
    const float* W4        = (const float*)d_in[10];
    const float* b4        = (const float*)d_in[11];
    const float* log_beta  = (const float*)d_in[12];
    const float* log_delta = (const float*)d_in[13];
    float* out = (float*)d_out;

    const int B = in_sizes[1];
    const int grid = B / ROWSPB;

    prep_weights<<<96, 1024>>>(W2, W3);

    cudaFuncSetAttribute(mdp_mma_kernel,
                         cudaFuncAttributeMaxDynamicSharedMemorySize, SMEM_BYTES);

    mdp_mma_kernel<<<grid, THREADS, SMEM_BYTES>>>(
        log_p, log_y, log_xb, log_q,
        W1, b1, b2, b3, W4, b4,
        log_beta, log_delta, out);
}